// round 1
// baseline (speedup 1.0000x reference)
#include <cuda_runtime.h>

#define N_EMB   512
#define EMB_D   64
#define HWSZ    4096          // H*W = 64*64
#define NTOK    131072        // 32 * 64 * 64
#define WS_STRIDE 80          // padded smem row (floats) for transposed weight

// Output packing (float32, reference tuple order)
#define OFF_RES 0ULL                       // result: 32*64*64*64 = 8388608
#define OFF_ARG 8388608ULL                 // argmin: 131072
#define OFF_W   8519680ULL                 // new_weight: 64*512
#define OFF_CS  8552448ULL                 // new_cluster_size: 512
#define OFF_EA  8552960ULL                 // new_embed_avg: 64*512

#define SMEM_BYTES ((N_EMB * WS_STRIDE + N_EMB) * 4)

// Scratch (allocation-free rule: __device__ globals). Re-zeroed every launch.
__device__ float g_hist[N_EMB];
__device__ float g_esum[EMB_D * N_EMB];
__device__ float g_ww[N_EMB];

__device__ __forceinline__ unsigned long long ffma2(unsigned long long a,
                                                    unsigned long long b,
                                                    unsigned long long c) {
    unsigned long long d;
    asm("fma.rn.f32x2 %0, %1, %2, %3;" : "=l"(d) : "l"(a), "l"(b), "l"(c));
    return d;
}

__device__ __forceinline__ unsigned long long pack2(float lo, float hi) {
    unsigned long long r;
    asm("mov.b64 %0, {%1, %2};" : "=l"(r)
        : "r"(__float_as_uint(lo)), "r"(__float_as_uint(hi)));
    return r;
}

__device__ __forceinline__ void unpack2(unsigned long long v, float& lo, float& hi) {
    unsigned int a, b;
    asm("mov.b64 {%0, %1}, %2;" : "=r"(a), "=r"(b) : "l"(v));
    lo = __uint_as_float(a);
    hi = __uint_as_float(b);
}

// ---------------------------------------------------------------------------
// prep: zero scratch, precompute ||w_j||^2
// ---------------------------------------------------------------------------
__global__ void prep_kernel(const float* __restrict__ w) {
    int idx = blockIdx.x * blockDim.x + threadIdx.x;
    if (idx < EMB_D * N_EMB) g_esum[idx] = 0.0f;
    if (idx < N_EMB) {
        g_hist[idx] = 0.0f;
        float s = 0.0f;
        #pragma unroll
        for (int d = 0; d < EMB_D; d++) {
            float v = w[d * N_EMB + idx];
            s = __fadd_rn(s, __fmul_rn(v, v));   // square-then-sum like jnp
        }
        g_ww[idx] = s;
    }
}

// ---------------------------------------------------------------------------
// assign: per-token argmin over 512 codewords + gather + EMA atomics
// 256 threads/block, 1 token/thread, 512 blocks. Weight staged to SMEM
// transposed (j-major) so the hot loop is pure LDS.64 + FFMA2.
// ---------------------------------------------------------------------------
extern __shared__ float smem_dyn[];

__global__ void __launch_bounds__(256, 1)
assign_kernel(const float* __restrict__ x,
              const float* __restrict__ w,
              float* __restrict__ out) {
    float* w_s  = smem_dyn;                       // [512][WS_STRIDE]
    float* ww_s = smem_dyn + N_EMB * WS_STRIDE;   // [512]

    int tid = threadIdx.x;

    // Stage weight transposed: w_s[j][d] = weight[d][j]
    for (int idx = tid; idx < EMB_D * N_EMB; idx += 256) {
        int d = idx >> 9;
        int j = idx & (N_EMB - 1);
        w_s[j * WS_STRIDE + d] = w[idx];
    }
    for (int j = tid; j < N_EMB; j += 256) ww_s[j] = g_ww[j];
    __syncthreads();

    int t  = blockIdx.x * 256 + tid;      // token id
    int b  = t >> 12;                      // batch
    int hw = t & (HWSZ - 1);               // h*64+w
    const float* xb = x + (size_t)b * EMB_D * HWSZ + hw;

    // Load token features into packed f32x2 pairs; compute ||x||^2
    unsigned long long xp[EMB_D / 2];
    float xx = 0.0f;
    #pragma unroll
    for (int i = 0; i < EMB_D / 2; i++) {
        float a = xb[(2 * i)     * HWSZ];
        float c = xb[(2 * i + 1) * HWSZ];
        xx = __fadd_rn(xx, __fmul_rn(a, a));
        xx = __fadd_rn(xx, __fmul_rn(c, c));
        xp[i] = pack2(a, c);
    }

    float best = 3.4e38f;
    int   bi   = 0;

    #pragma unroll 1
    for (int j0 = 0; j0 < N_EMB; j0 += 4) {
        const unsigned long long* r0 =
            (const unsigned long long*)(w_s + (j0 + 0) * WS_STRIDE);
        const unsigned long long* r1 =
            (const unsigned long long*)(w_s + (j0 + 1) * WS_STRIDE);
        const unsigned long long* r2 =
            (const unsigned long long*)(w_s + (j0 + 2) * WS_STRIDE);
        const unsigned long long* r3 =
            (const unsigned long long*)(w_s + (j0 + 3) * WS_STRIDE);

        unsigned long long a0 = 0ULL, a1 = 0ULL, a2 = 0ULL, a3 = 0ULL;
        #pragma unroll
        for (int q = 0; q < EMB_D / 2; q++) {
            unsigned long long xq = xp[q];
            a0 = ffma2(xq, r0[q], a0);
            a1 = ffma2(xq, r1[q], a1);
            a2 = ffma2(xq, r2[q], a2);
            a3 = ffma2(xq, r3[q], a3);
        }

        float lo, hi;
        unpack2(a0, lo, hi);
        float dot0 = __fadd_rn(lo, hi);
        unpack2(a1, lo, hi);
        float dot1 = __fadd_rn(lo, hi);
        unpack2(a2, lo, hi);
        float dot2 = __fadd_rn(lo, hi);
        unpack2(a3, lo, hi);
        float dot3 = __fadd_rn(lo, hi);

        // dist = (xx - 2*dot) + ||w||^2, op-by-op rounded like the reference
        float d0 = __fadd_rn(__fsub_rn(xx, __fmul_rn(2.0f, dot0)), ww_s[j0 + 0]);
        float d1 = __fadd_rn(__fsub_rn(xx, __fmul_rn(2.0f, dot1)), ww_s[j0 + 1]);
        float d2 = __fadd_rn(__fsub_rn(xx, __fmul_rn(2.0f, dot2)), ww_s[j0 + 2]);
        float d3 = __fadd_rn(__fsub_rn(xx, __fmul_rn(2.0f, dot3)), ww_s[j0 + 3]);

        // strict < in ascending j => first-min tie-break, matching jnp.argmin
        if (d0 < best) { best = d0; bi = j0 + 0; }
        if (d1 < best) { best = d1; bi = j0 + 1; }
        if (d2 < best) { best = d2; bi = j0 + 2; }
        if (d3 < best) { best = d3; bi = j0 + 3; }
    }

    // argmin output (as float)
    out[OFF_ARG + (size_t)t] = (float)bi;

    // quantized result: out[b][d][h][w] = weight[d][bi]
    float* ro = out + (size_t)b * EMB_D * HWSZ + hw;
    #pragma unroll
    for (int d = 0; d < EMB_D; d++) {
        ro[d * HWSZ] = __ldg(&w[d * N_EMB + bi]);
    }

    // EMA accumulators
    atomicAdd(&g_hist[bi], 1.0f);
    #pragma unroll
    for (int i = 0; i < EMB_D / 2; i++) {
        float lo, hi;
        unpack2(xp[i], lo, hi);
        atomicAdd(&g_esum[(2 * i)     * N_EMB + bi], lo);
        atomicAdd(&g_esum[(2 * i + 1) * N_EMB + bi], hi);
    }
}

// ---------------------------------------------------------------------------
// finalize: EMA update of cluster_size / embed_avg / weight
// ---------------------------------------------------------------------------
__global__ void finalize_kernel(const float* __restrict__ cs_in,
                                const float* __restrict__ ea_in,
                                float* __restrict__ out) {
    __shared__ float red[N_EMB];
    int j = threadIdx.x;

    const float DEC = 0.99f;
    const float OMD = (float)(1.0 - 0.99);          // matches python double->f32
    const float EPSF = (float)1e-5;
    const float NEPS = (float)(N_EMB * 1e-5);

    float nidx = g_hist[j];
    if (nidx == 0.0f) nidx = 1.0f;
    float ncs = __fadd_rn(__fmul_rn(DEC, cs_in[j]), __fmul_rn(OMD, nidx));

    red[j] = ncs;
    __syncthreads();
    #pragma unroll
    for (int s = N_EMB / 2; s > 0; s >>= 1) {
        if (j < s) red[j] += red[j + s];
        __syncthreads();
    }
    float n = red[0];

    float csn = __fmul_rn(__fdiv_rn(__fadd_rn(ncs, EPSF), __fadd_rn(n, NEPS)), n);

    out[OFF_CS + j] = ncs;

    for (int d = 0; d < EMB_D; d++) {
        int idx = d * N_EMB + j;
        float e = __fadd_rn(__fmul_rn(DEC, ea_in[idx]), __fmul_rn(OMD, g_esum[idx]));
        out[OFF_EA + idx] = e;
        out[OFF_W  + idx] = __fdiv_rn(e, csn);
    }
}

// ---------------------------------------------------------------------------
extern "C" void kernel_launch(void* const* d_in, const int* in_sizes, int n_in,
                              void* d_out, int out_size) {
    const float* x  = (const float*)d_in[0];  // (32, 64, 64, 64)
    const float* w  = (const float*)d_in[1];  // (64, 512)
    const float* cs = (const float*)d_in[2];  // (512,)
    const float* ea = (const float*)d_in[3];  // (64, 512)
    float* out = (float*)d_out;

    cudaFuncSetAttribute(assign_kernel,
                         cudaFuncAttributeMaxDynamicSharedMemorySize, SMEM_BYTES);

    prep_kernel<<<130, 256>>>(w);
    assign_kernel<<<NTOK / 256, 256, SMEM_BYTES>>>(x, w, out);
    finalize_kernel<<<1, N_EMB>>>(cs, ea, out);
}

// round 2
// speedup vs baseline: 1.1285x; 1.1285x over previous
#include <cuda_runtime.h>

#define N_EMB   512
#define EMB_D   64
#define HWSZ    4096          // H*W
#define NTOK    131072        // 32 * 64 * 64
#define NCHUNK  (NTOK / 256)  // 512 work chunks of 256 tokens

// Output packing (float32, reference tuple order)
#define OFF_RES 0ULL
#define OFF_ARG 8388608ULL
#define OFF_W   8519680ULL
#define OFF_CS  8552448ULL
#define OFF_EA  8552960ULL

#define SMEM_BYTES ((N_EMB * EMB_D + N_EMB) * 4)   // 133120 B

// Scratch (__device__ globals — allocation-free rule)
__device__ float g_hist[N_EMB];
__device__ float g_esum[EMB_D * N_EMB];
__device__ float g_ww[N_EMB];
__device__ float g_wt[N_EMB * EMB_D];   // weight transposed: [j][d]
__device__ unsigned int g_work;

__device__ __forceinline__ unsigned long long ffma2(unsigned long long a,
                                                    unsigned long long b,
                                                    unsigned long long c) {
    unsigned long long d;
    asm("fma.rn.f32x2 %0, %1, %2, %3;" : "=l"(d) : "l"(a), "l"(b), "l"(c));
    return d;
}

__device__ __forceinline__ unsigned long long pack2(float lo, float hi) {
    unsigned long long r;
    asm("mov.b64 %0, {%1, %2};" : "=l"(r)
        : "r"(__float_as_uint(lo)), "r"(__float_as_uint(hi)));
    return r;
}

__device__ __forceinline__ void unpack2(unsigned long long v, float& lo, float& hi) {
    unsigned int a, b;
    asm("mov.b64 {%0, %1}, %2;" : "=r"(a), "=r"(b) : "l"(v));
    lo = __uint_as_float(a);
    hi = __uint_as_float(b);
}

// ---------------------------------------------------------------------------
// prep: zero scratch, transpose weight, precompute ||w_j||^2, reset work ctr
// ---------------------------------------------------------------------------
__global__ void prep_kernel(const float* __restrict__ w) {
    int idx = blockIdx.x * blockDim.x + threadIdx.x;
    if (idx == 0) g_work = 0u;
    if (idx < EMB_D * N_EMB) {
        g_esum[idx] = 0.0f;
        int j = idx >> 6;           // idx = j*64 + d
        int d = idx & 63;
        g_wt[idx] = w[d * N_EMB + j];
    }
    if (idx < N_EMB) {
        g_hist[idx] = 0.0f;
        float s = 0.0f;
        #pragma unroll
        for (int d = 0; d < EMB_D; d++) {
            float v = w[d * N_EMB + idx];
            s = __fadd_rn(s, __fmul_rn(v, v));
        }
        g_ww[idx] = s;
    }
}

// ---------------------------------------------------------------------------
// assign: persistent CTAs, work-steal over 512 chunks of 256 tokens.
// Weight staged to SMEM once per CTA (transposed, compact [512][64]).
// Hot loop: LDS.128 (broadcast) + FFMA2, 4 rows x 2 accumulators.
// ---------------------------------------------------------------------------
extern __shared__ float smem_dyn[];

__global__ void __launch_bounds__(256, 1)
assign_kernel(const float* __restrict__ x,
              float* __restrict__ out) {
    float* w_s  = smem_dyn;                     // [512][64] j-major
    float* ww_s = smem_dyn + N_EMB * EMB_D;     // [512]
    __shared__ int s_chunk;

    int tid = threadIdx.x;

    // Stage transposed weight: coalesced float4 copy, conflict-free
    {
        const float4* src = (const float4*)g_wt;
        float4* dst = (float4*)w_s;
        #pragma unroll
        for (int i = 0; i < (N_EMB * EMB_D / 4) / 256; i++)
            dst[i * 256 + tid] = src[i * 256 + tid];
        for (int j = tid; j < N_EMB; j += 256) ww_s[j] = g_ww[j];
    }

    for (;;) {
        __syncthreads();
        if (tid == 0) s_chunk = (int)atomicAdd(&g_work, 1u);
        __syncthreads();
        int c = s_chunk;
        if (c >= NCHUNK) break;

        int t  = c * 256 + tid;           // token id
        int b  = t >> 12;
        int hw = t & (HWSZ - 1);
        const float* xb = x + (size_t)b * EMB_D * HWSZ + hw;

        // Token features -> packed f32x2; ||x||^2
        unsigned long long xp[EMB_D / 2];
        float xx = 0.0f;
        #pragma unroll
        for (int i = 0; i < EMB_D / 2; i++) {
            float a  = xb[(2 * i)     * HWSZ];
            float cc = xb[(2 * i + 1) * HWSZ];
            xx = __fadd_rn(xx, __fmul_rn(a, a));
            xx = __fadd_rn(xx, __fmul_rn(cc, cc));
            xp[i] = pack2(a, cc);
        }

        float best = 3.4e38f;
        int   bi   = 0;

        #pragma unroll 1
        for (int j0 = 0; j0 < N_EMB; j0 += 4) {
            const ulonglong2* r0 = (const ulonglong2*)(w_s + (j0 + 0) * EMB_D);
            const ulonglong2* r1 = (const ulonglong2*)(w_s + (j0 + 1) * EMB_D);
            const ulonglong2* r2 = (const ulonglong2*)(w_s + (j0 + 2) * EMB_D);
            const ulonglong2* r3 = (const ulonglong2*)(w_s + (j0 + 3) * EMB_D);

            unsigned long long a0e = 0ULL, a0o = 0ULL, a1e = 0ULL, a1o = 0ULL;
            unsigned long long a2e = 0ULL, a2o = 0ULL, a3e = 0ULL, a3o = 0ULL;

            #pragma unroll
            for (int q = 0; q < EMB_D / 4; q++) {      // 16 LDS.128 per row
                ulonglong2 v0 = r0[q];
                ulonglong2 v1 = r1[q];
                ulonglong2 v2 = r2[q];
                ulonglong2 v3 = r3[q];
                unsigned long long xa = xp[2 * q];
                unsigned long long xb2 = xp[2 * q + 1];
                a0e = ffma2(xa, v0.x, a0e);  a0o = ffma2(xb2, v0.y, a0o);
                a1e = ffma2(xa, v1.x, a1e);  a1o = ffma2(xb2, v1.y, a1o);
                a2e = ffma2(xa, v2.x, a2e);  a2o = ffma2(xb2, v2.y, a2o);
                a3e = ffma2(xa, v3.x, a3e);  a3o = ffma2(xb2, v3.y, a3o);
            }

            float lo, hi, lo2, hi2;
            unpack2(a0e, lo, hi);  unpack2(a0o, lo2, hi2);
            float dot0 = __fadd_rn(__fadd_rn(lo, hi), __fadd_rn(lo2, hi2));
            unpack2(a1e, lo, hi);  unpack2(a1o, lo2, hi2);
            float dot1 = __fadd_rn(__fadd_rn(lo, hi), __fadd_rn(lo2, hi2));
            unpack2(a2e, lo, hi);  unpack2(a2o, lo2, hi2);
            float dot2 = __fadd_rn(__fadd_rn(lo, hi), __fadd_rn(lo2, hi2));
            unpack2(a3e, lo, hi);  unpack2(a3o, lo2, hi2);
            float dot3 = __fadd_rn(__fadd_rn(lo, hi), __fadd_rn(lo2, hi2));

            float d0 = __fadd_rn(__fsub_rn(xx, __fmul_rn(2.0f, dot0)), ww_s[j0 + 0]);
            float d1 = __fadd_rn(__fsub_rn(xx, __fmul_rn(2.0f, dot1)), ww_s[j0 + 1]);
            float d2 = __fadd_rn(__fsub_rn(xx, __fmul_rn(2.0f, dot2)), ww_s[j0 + 2]);
            float d3 = __fadd_rn(__fsub_rn(xx, __fmul_rn(2.0f, dot3)), ww_s[j0 + 3]);

            if (d0 < best) { best = d0; bi = j0 + 0; }
            if (d1 < best) { best = d1; bi = j0 + 1; }
            if (d2 < best) { best = d2; bi = j0 + 2; }
            if (d3 < best) { best = d3; bi = j0 + 3; }
        }

        // argmin (as float)
        out[OFF_ARG + (size_t)t] = (float)bi;

        // quantized result from smem codebook
        float* ro = out + (size_t)b * EMB_D * HWSZ + hw;
        const float4* wrow = (const float4*)(w_s + bi * EMB_D);
        #pragma unroll
        for (int i = 0; i < EMB_D / 4; i++) {
            float4 v = wrow[i];
            ro[(4 * i + 0) * HWSZ] = v.x;
            ro[(4 * i + 1) * HWSZ] = v.y;
            ro[(4 * i + 2) * HWSZ] = v.z;
            ro[(4 * i + 3) * HWSZ] = v.w;
        }

        // EMA accumulators
        atomicAdd(&g_hist[bi], 1.0f);
        #pragma unroll
        for (int i = 0; i < EMB_D / 2; i++) {
            float lo, hi;
            unpack2(xp[i], lo, hi);
            atomicAdd(&g_esum[(2 * i)     * N_EMB + bi], lo);
            atomicAdd(&g_esum[(2 * i + 1) * N_EMB + bi], hi);
        }
    }
}

// ---------------------------------------------------------------------------
// finalize: EMA update
// ---------------------------------------------------------------------------
__global__ void finalize_kernel(const float* __restrict__ cs_in,
                                const float* __restrict__ ea_in,
                                float* __restrict__ out) {
    __shared__ float red[N_EMB];
    int j = threadIdx.x;

    const float DEC = 0.99f;
    const float OMD = (float)(1.0 - 0.99);
    const float EPSF = (float)1e-5;
    const float NEPS = (float)(N_EMB * 1e-5);

    float nidx = g_hist[j];
    if (nidx == 0.0f) nidx = 1.0f;
    float ncs = __fadd_rn(__fmul_rn(DEC, cs_in[j]), __fmul_rn(OMD, nidx));

    red[j] = ncs;
    __syncthreads();
    #pragma unroll
    for (int s = N_EMB / 2; s > 0; s >>= 1) {
        if (j < s) red[j] += red[j + s];
        __syncthreads();
    }
    float n = red[0];

    float csn = __fmul_rn(__fdiv_rn(__fadd_rn(ncs, EPSF), __fadd_rn(n, NEPS)), n);

    out[OFF_CS + j] = ncs;

    for (int d = 0; d < EMB_D; d++) {
        int idx = d * N_EMB + j;
        float e = __fadd_rn(__fmul_rn(DEC, ea_in[idx]), __fmul_rn(OMD, g_esum[idx]));
        out[OFF_EA + idx] = e;
        out[OFF_W  + idx] = __fdiv_rn(e, csn);
    }
}

// ---------------------------------------------------------------------------
extern "C" void kernel_launch(void* const* d_in, const int* in_sizes, int n_in,
                              void* d_out, int out_size) {
    const float* x  = (const float*)d_in[0];
    const float* w  = (const float*)d_in[1];
    const float* cs = (const float*)d_in[2];
    const float* ea = (const float*)d_in[3];
    float* out = (float*)d_out;

    cudaFuncSetAttribute(assign_kernel,
                         cudaFuncAttributeMaxDynamicSharedMemorySize, SMEM_BYTES);

    prep_kernel<<<128, 256>>>(w);
    assign_kernel<<<148, 256, SMEM_BYTES>>>(x, out);
    finalize_kernel<<<1, N_EMB>>>(cs, ea, out);
}